// round 1
// baseline (speedup 1.0000x reference)
#include <cuda_runtime.h>

#define RTYPES 8
#define TTYPES 4
#define CSZ 64
#define MCAP 10000
#define ECAP 100000
#define PCAP (ECAP + 2*RTYPES*CSZ)

// Scratch (device globals: no runtime allocation allowed)
__device__ float g_num[MCAP*128];   // softmax numerator  sum(v*ex) per dst
__device__ float g_denom[MCAP*8];   // softmax denominator per dst, per head
__device__ int   g_perm[PCAP];      // edges bucketed by etype, CSZ-aligned buckets, -1 pad
__device__ int   g_counts[RTYPES];
__device__ int   g_cursor[RTYPES];

__device__ __forceinline__ float warp_sum(float v) {
#pragma unroll
  for (int o = 16; o; o >>= 1) v += __shfl_xor_sync(0xffffffffu, v, o);
  return v;
}

__global__ void k_init(int M, int EP) {
  int i = blockIdx.x * blockDim.x + threadIdx.x;
  if (i < M*128) g_num[i] = 0.f;
  if (i < M*8)   g_denom[i] = 0.f;
  if (i < EP)    g_perm[i] = -1;
  if (i < RTYPES) { g_counts[i] = 0; g_cursor[i] = 0; }
}

__global__ void k_count(const int* __restrict__ etype, int E) {
  int i = blockIdx.x*blockDim.x + threadIdx.x;
  if (i < E) atomicAdd(&g_counts[etype[i]], 1);
}

__global__ void k_scan() {
  int b = 0;
  for (int r = 0; r < RTYPES; ++r) {
    g_cursor[r] = b;
    b += ((g_counts[r] + CSZ - 1) / CSZ) * CSZ;
  }
}

__global__ void k_scatter(const int* __restrict__ etype, int E) {
  int i = blockIdx.x*blockDim.x + threadIdx.x;
  if (i < E) {
    int pos = atomicAdd(&g_cursor[etype[i]], 1);
    g_perm[pos] = i;
  }
}

// Main edge kernel: one CTA = 64 edges of a single etype.
// Phase A: gather + time-encode + LayerNorm dia_d(128), dia_s(160) into SMEM.
// Phase B: stage Wq -> q(regs); stage Wk -> k(regs); a = q.k -> ex (no max
// shift: logits are O(1) after LN); stage Wv -> v(regs); scatter ex and v*ex.
__global__ void __launch_bounds__(256, 1) k_edge(
    const float* __restrict__ src_h, const float* __restrict__ src_tw,
    const float* __restrict__ src_tb, const float* __restrict__ edge_h,
    const float* __restrict__ date, const int* __restrict__ src_idx,
    const int* __restrict__ dst_idx, const int* __restrict__ etype,
    const float* __restrict__ Wq, const float* __restrict__ Wk,
    const float* __restrict__ Wv,
    const float* __restrict__ sg, const float* __restrict__ sb,
    const float* __restrict__ dg, const float* __restrict__ db)
{
  extern __shared__ float smem[];
  float* sW    = smem;              // 160*128 = 20480 floats (staged Wq/Wk/Wv)
  float* sDiaD = sW + 20480;        // 64*128
  float* sDiaS = sDiaD + 8192;      // 64*160
  float* sEx   = sDiaS + 10240;     // 64*8
  int*   sEid  = (int*)(sEx + 512); // 64
  int*   sDst  = sEid + 64;         // 64
  int*   sMeta = sDst + 64;         // 1

  const int tid = threadIdx.x;
  if (tid < CSZ) {
    int e = g_perm[blockIdx.x*CSZ + tid];
    sEid[tid] = e;
    sDst[tid] = (e >= 0) ? dst_idx[e] : 0;
  }
  if (tid == 0) {
    int e0 = g_perm[blockIdx.x*CSZ];
    sMeta[0] = (e0 >= 0) ? etype[e0] : -1;
  }
  __syncthreads();
  const int et = sMeta[0];
  if (et < 0) return;   // pure-padding chunk

  const int warp = tid >> 5, lane = tid & 31;

  // ---------------- Phase A: dia + LayerNorm ----------------
  for (int c = warp; c < CSZ; c += 8) {
    const int e = sEid[c];
    if (e < 0) {
#pragma unroll
      for (int kk = 0; kk < 4; ++kk) sDiaD[c*128 + lane + 32*kk] = 0.f;
#pragma unroll
      for (int kk = 0; kk < 5; ++kk) sDiaS[c*160 + lane + 32*kk] = 0.f;
      continue;
    }
    const float t = date[e];
    const int s = src_idx[e];
    const int d = sDst[c];

    // dst side (128 dims)
    float xd[4];
#pragma unroll
    for (int kk = 0; kk < 4; ++kk) xd[kk] = src_h[d*128 + lane + 32*kk];
    xd[0] *= __sinf(src_tw[d*32+lane]*t + src_tb[d*32+lane]);
    float mu = warp_sum(xd[0]+xd[1]+xd[2]+xd[3]) * (1.f/128.f);
    float vv = 0.f;
#pragma unroll
    for (int kk = 0; kk < 4; ++kk) { float dl = xd[kk]-mu; vv = fmaf(dl,dl,vv); }
    float rs = rsqrtf(warp_sum(vv)*(1.f/128.f) + 1e-5f);
#pragma unroll
    for (int kk = 0; kk < 4; ++kk) {
      int i = lane + 32*kk;
      sDiaD[c*128+i] = (xd[kk]-mu)*rs*dg[i] + db[i];
    }

    // src side (160 dims = 32 time-encoded + 96 + 32 edge_h)
    float xs[5];
#pragma unroll
    for (int kk = 0; kk < 4; ++kk) xs[kk] = src_h[s*128 + lane + 32*kk];
    xs[0] *= __sinf(src_tw[s*32+lane]*t + src_tb[s*32+lane]);
    xs[4] = edge_h[e*32 + lane];
    mu = warp_sum(xs[0]+xs[1]+xs[2]+xs[3]+xs[4]) * (1.f/160.f);
    vv = 0.f;
#pragma unroll
    for (int kk = 0; kk < 5; ++kk) { float dl = xs[kk]-mu; vv = fmaf(dl,dl,vv); }
    rs = rsqrtf(warp_sum(vv)*(1.f/160.f) + 1e-5f);
#pragma unroll
    for (int kk = 0; kk < 5; ++kk) {
      int i = lane + 32*kk;
      sDiaS[c*160+i] = (xs[kk]-mu)*rs*sg[i] + sb[i];
    }
  }
  __syncthreads();

  // ---------------- Phase B: q/k/v matvecs ----------------
  const int j  = tid & 127;      // output column
  const int cb = (tid >> 7) * 32; // half of the 64 edges this thread owns
  const int h  = j >> 4;          // head

  // ---- q = LN(dia_d) @ Wq[et]
  {
    const float4* srcw = (const float4*)(Wq + et*16384);
    for (int idx = tid; idx < 4096; idx += 256) ((float4*)sW)[idx] = srcw[idx];
  }
  __syncthreads();
  float q[32];
#pragma unroll
  for (int c = 0; c < 32; ++c) q[c] = 0.f;
  for (int i = 0; i < 128; i += 4) {
    float w0 = sW[(i+0)*128+j], w1 = sW[(i+1)*128+j];
    float w2 = sW[(i+2)*128+j], w3 = sW[(i+3)*128+j];
#pragma unroll
    for (int c = 0; c < 32; ++c) {
      float4 d4 = *(const float4*)&sDiaD[(cb+c)*128 + i];
      q[c] = fmaf(d4.x, w0, fmaf(d4.y, w1, fmaf(d4.z, w2, fmaf(d4.w, w3, q[c]))));
    }
  }
  __syncthreads();

  // ---- k = LN(dia_s) @ Wk[et]
  {
    const float4* srcw = (const float4*)(Wk + et*20480);
    for (int idx = tid; idx < 5120; idx += 256) ((float4*)sW)[idx] = srcw[idx];
  }
  __syncthreads();
  float acc[32];
#pragma unroll
  for (int c = 0; c < 32; ++c) acc[c] = 0.f;
  for (int i = 0; i < 160; i += 4) {
    float w0 = sW[(i+0)*128+j], w1 = sW[(i+1)*128+j];
    float w2 = sW[(i+2)*128+j], w3 = sW[(i+3)*128+j];
#pragma unroll
    for (int c = 0; c < 32; ++c) {
      float4 d4 = *(const float4*)&sDiaS[(cb+c)*160 + i];
      acc[c] = fmaf(d4.x, w0, fmaf(d4.y, w1, fmaf(d4.z, w2, fmaf(d4.w, w3, acc[c]))));
    }
  }

  // ---- logits a = sum_head(q*k)/sqrt(128) -> ex; accumulate denominators
#pragma unroll
  for (int c = 0; c < 32; ++c) {
    float p = q[c]*acc[c];
    p += __shfl_xor_sync(0xffffffffu, p, 1);
    p += __shfl_xor_sync(0xffffffffu, p, 2);
    p += __shfl_xor_sync(0xffffffffu, p, 4);
    p += __shfl_xor_sync(0xffffffffu, p, 8);
    if ((lane & 15) == 0) {
      float ex = __expf(p * 0.0883883476483184f);  // 1/sqrt(128)
      sEx[(cb+c)*8 + h] = ex;
      if (sEid[cb+c] >= 0)
        atomicAdd(&g_denom[sDst[cb+c]*8 + h], ex);
    }
  }
  __syncthreads();

  // ---- v = LN(dia_s) @ Wv[et]; scatter v*ex into numerators
  {
    const float4* srcw = (const float4*)(Wv + et*20480);
    for (int idx = tid; idx < 5120; idx += 256) ((float4*)sW)[idx] = srcw[idx];
  }
  __syncthreads();
#pragma unroll
  for (int c = 0; c < 32; ++c) q[c] = 0.f;  // reuse q[] as v accumulator
  for (int i = 0; i < 160; i += 4) {
    float w0 = sW[(i+0)*128+j], w1 = sW[(i+1)*128+j];
    float w2 = sW[(i+2)*128+j], w3 = sW[(i+3)*128+j];
#pragma unroll
    for (int c = 0; c < 32; ++c) {
      float4 d4 = *(const float4*)&sDiaS[(cb+c)*160 + i];
      q[c] = fmaf(d4.x, w0, fmaf(d4.y, w1, fmaf(d4.z, w2, fmaf(d4.w, w3, q[c]))));
    }
  }
#pragma unroll
  for (int c = 0; c < 32; ++c) {
    const int cc = cb + c;
    if (sEid[cc] >= 0)
      atomicAdd(&g_num[sDst[cc]*128 + j], q[c] * sEx[cc*8 + h]);
  }
}

// Output kernel: softmax divide + bias + typed linear (Wa staged in SMEM,
// blocked by node type via gridDim.y) + gated skip blend.
__global__ void __launch_bounds__(128) k_out(
    const float* __restrict__ src_h, const int* __restrict__ ntype,
    const float* __restrict__ Wa, const float* __restrict__ h_bias,
    const float* __restrict__ skip, float* __restrict__ out, int M)
{
  extern __shared__ float smem[];
  float* sWa = smem;          // 128*128
  float* sh  = smem + 16384;  // 128
  const int tt  = blockIdx.y;
  const int tid = threadIdx.x;
  {
    const float4* srcw = (const float4*)(Wa + tt*16384);
    for (int idx = tid; idx < 4096; idx += 128) ((float4*)sWa)[idx] = srcw[idx];
  }
  const float gate = 1.f / (1.f + __expf(-skip[tt]));
  const float bias = h_bias[tt*128 + tid];
  __syncthreads();

  const int m1 = min((blockIdx.x + 1) * CSZ, M);
  for (int m = blockIdx.x * CSZ; m < m1; ++m) {
    if (ntype[m] != tt) continue;          // uniform across block
    float dden = g_denom[m*8 + (tid >> 4)];
    float hv = (dden > 0.f) ? g_num[m*128 + tid] / dden : 0.f;  // isolated nodes
    sh[tid] = hv + bias;
    __syncthreads();
    float a0 = 0.f;
#pragma unroll 4
    for (int i = 0; i < 128; ++i)
      a0 = fmaf(sh[i], sWa[i*128 + tid], a0);
    out[m*128 + tid] = a0*gate + src_h[m*128 + tid]*(1.f - gate);
    __syncthreads();
  }
}

extern "C" void kernel_launch(void* const* d_in, const int* in_sizes, int n_in,
                              void* d_out, int out_size) {
  const float* src_h  = (const float*)d_in[0];
  const float* src_tw = (const float*)d_in[1];
  const float* src_tb = (const float*)d_in[2];
  const float* edge_h = (const float*)d_in[3];
  const float* date   = (const float*)d_in[4];
  const int*   src_idx= (const int*)d_in[5];
  const int*   dst_idx= (const int*)d_in[6];
  const int*   etype  = (const int*)d_in[7];
  const int*   ntype  = (const int*)d_in[8];
  const float* Wq     = (const float*)d_in[9];
  const float* Wk     = (const float*)d_in[10];
  const float* Wv     = (const float*)d_in[11];
  const float* Wa     = (const float*)d_in[12];
  const float* h_bias = (const float*)d_in[13];
  const float* skip   = (const float*)d_in[14];
  const float* sg     = (const float*)d_in[15];
  const float* sb     = (const float*)d_in[16];
  const float* dg     = (const float*)d_in[17];
  const float* db     = (const float*)d_in[18];
  float* out = (float*)d_out;

  const int E = in_sizes[4];   // date
  const int M = in_sizes[8];   // ntype
  const int T = in_sizes[14];  // skip

  const int SMEM1 = (20480 + 8192 + 10240 + 512) * 4 + 132 * 4; // ~158 KB
  const int SMEM3 = (16384 + 128) * 4;                          // ~66 KB
  cudaFuncSetAttribute(k_edge, cudaFuncAttributeMaxDynamicSharedMemorySize, SMEM1);
  cudaFuncSetAttribute(k_out,  cudaFuncAttributeMaxDynamicSharedMemorySize, SMEM3);

  int initN = M * 128; if (PCAP > initN) initN = PCAP;
  k_init<<<(initN + 255)/256, 256>>>(M, PCAP);
  k_count<<<(E + 255)/256, 256>>>(etype, E);
  k_scan<<<1, 1>>>();
  k_scatter<<<(E + 255)/256, 256>>>(etype, E);

  const int nb1 = (E + CSZ - 1)/CSZ + RTYPES;
  k_edge<<<nb1, 256, SMEM1>>>(src_h, src_tw, src_tb, edge_h, date,
                              src_idx, dst_idx, etype, Wq, Wk, Wv,
                              sg, sb, dg, db);

  dim3 g3((M + CSZ - 1)/CSZ, T);
  k_out<<<g3, 128, SMEM3>>>(src_h, ntype, Wa, h_bias, skip, out, M);
}

// round 2
// speedup vs baseline: 1.0924x; 1.0924x over previous
#include <cuda_runtime.h>

#define RTYPES 8
#define TTYPES 4
#define CSZ 64
#define MCAP 10000
#define ECAP 100000
#define PCAP (ECAP + 2*RTYPES*CSZ)

// Scratch (device globals: no runtime allocation allowed)
__device__ float g_num[MCAP*128];   // softmax numerator  sum(v*ex) per dst
__device__ float g_denom[MCAP*8];   // softmax denominator per dst, per head
__device__ int   g_perm[PCAP];      // edges bucketed by etype, CSZ-aligned, -1 pad
__device__ int   g_counts[RTYPES];
__device__ int   g_cursor[RTYPES];

typedef unsigned long long ull;

__device__ __forceinline__ float warp_sum(float v) {
#pragma unroll
  for (int o = 16; o; o >>= 1) v += __shfl_xor_sync(0xffffffffu, v, o);
  return v;
}

// ---- packed fp32x2 helpers (Blackwell FFMA2 path; PTX-only) ----
__device__ __forceinline__ void ffma2(ull& acc, ull a, ull b) {
  asm("fma.rn.f32x2 %0, %1, %2, %3;" : "=l"(acc) : "l"(a), "l"(b), "l"(acc));
}
__device__ __forceinline__ ull fmul2(ull a, ull b) {
  ull r; asm("mul.rn.f32x2 %0, %1, %2;" : "=l"(r) : "l"(a), "l"(b)); return r;
}
__device__ __forceinline__ ull fadd2(ull a, ull b) {
  ull r; asm("add.rn.f32x2 %0, %1, %2;" : "=l"(r) : "l"(a), "l"(b)); return r;
}
__device__ __forceinline__ ull splat2(float w) {
  ull r; asm("mov.b64 %0, {%1, %1};" : "=l"(r) : "f"(w)); return r;
}
__device__ __forceinline__ float2 unpk2(ull v) {
  float2 f; asm("mov.b64 {%0, %1}, %2;" : "=f"(f.x), "=f"(f.y) : "l"(v)); return f;
}
__device__ __forceinline__ void cp16(unsigned dst, const void* src) {
  asm volatile("cp.async.cg.shared.global [%0], [%1], 16;" :: "r"(dst), "l"(src));
}
#define CP_COMMIT() asm volatile("cp.async.commit_group;")
#define CP_WAIT0()  asm volatile("cp.async.wait_group 0;")

__global__ void k_init(int M, int EP) {
  int i = blockIdx.x * blockDim.x + threadIdx.x;
  if (i < M*128) g_num[i] = 0.f;
  if (i < M*8)   g_denom[i] = 0.f;
  if (i < EP)    g_perm[i] = -1;
  if (i < RTYPES) { g_counts[i] = 0; g_cursor[i] = 0; }
}

__global__ void k_count(const int* __restrict__ etype, int E) {
  __shared__ int loc[RTYPES];
  int t = threadIdx.x;
  if (t < RTYPES) loc[t] = 0;
  __syncthreads();
  for (int i = blockIdx.x*blockDim.x + t; i < E; i += gridDim.x*blockDim.x)
    atomicAdd(&loc[etype[i]], 1);
  __syncthreads();
  if (t < RTYPES && loc[t]) atomicAdd(&g_counts[t], loc[t]);
}

__global__ void k_scan() {
  int b = 0;
  for (int r = 0; r < RTYPES; ++r) {
    g_cursor[r] = b;
    b += ((g_counts[r] + CSZ - 1) / CSZ) * CSZ;
  }
}

// Block-aggregated scatter: 8 global atomics per CTA instead of per-edge.
__global__ void k_scatter(const int* __restrict__ etype, int E) {
  __shared__ int loc[RTYPES], base[RTYPES];
  const int t = threadIdx.x;
  if (t < RTYPES) loc[t] = 0;
  __syncthreads();
  const int start = blockIdx.x * 1024;
  const int end = min(start + 1024, E);
  for (int i = start + t; i < end; i += 256) atomicAdd(&loc[etype[i]], 1);
  __syncthreads();
  if (t < RTYPES) { base[t] = loc[t] ? atomicAdd(&g_cursor[t], loc[t]) : 0; loc[t] = 0; }
  __syncthreads();
  for (int i = start + t; i < end; i += 256) {
    int r = etype[i];
    int pos = base[r] + atomicAdd(&loc[r], 1);
    g_perm[pos] = i;
  }
}

// Main edge kernel: one CTA = 64 edges of one etype, 512 threads.
// smem: sWq(64KB) + sWkv(80KB) both cp.async-prefetched during Phase A;
// dia stored TRANSPOSED [i][edge] (pad 66) so edge-pairs load as LDS.64
// feeding packed fma.rn.f32x2.
__global__ void __launch_bounds__(512, 1) k_edge(
    const float* __restrict__ src_h, const float* __restrict__ src_tw,
    const float* __restrict__ src_tb, const float* __restrict__ edge_h,
    const float* __restrict__ date, const int* __restrict__ src_idx,
    const int* __restrict__ dst_idx, const int* __restrict__ etype,
    const float* __restrict__ Wq, const float* __restrict__ Wk,
    const float* __restrict__ Wv,
    const float* __restrict__ sg, const float* __restrict__ sb,
    const float* __restrict__ dg, const float* __restrict__ db)
{
  extern __shared__ float smem[];
  float* sWq  = smem;                 // 16384
  float* sWkv = sWq + 16384;          // 20480
  float* sDd  = sWkv + 20480;         // 128*66 = 8448  (transposed dia_d)
  float* sDs  = sDd + 8448;           // 160*66 = 10560 (transposed dia_s)
  float* sEx  = sDs + 10560;          // 64*8
  int*   sEid = (int*)(sEx + 512);    // 64
  int*   sDst = sEid + 64;            // 64
  int*   sMeta = sDst + 64;           // 1

  const int tid = threadIdx.x;
  if (tid < CSZ) {
    int e = g_perm[blockIdx.x*CSZ + tid];
    sEid[tid] = e;
    sDst[tid] = (e >= 0) ? dst_idx[e] : 0;
  }
  if (tid == 0) {
    int e0 = g_perm[blockIdx.x*CSZ];
    sMeta[0] = (e0 >= 0) ? etype[e0] : -1;
  }
  __syncthreads();
  const int et = sMeta[0];
  if (et < 0) return;   // pure-padding chunk

  // ---- prefetch Wq + Wk while Phase A runs ----
  {
    unsigned swq = (unsigned)__cvta_generic_to_shared(sWq);
    const float4* gq = (const float4*)(Wq + et*16384);
#pragma unroll
    for (int r = 0; r < 8; ++r) cp16(swq + (tid + r*512)*16, gq + tid + r*512);
    CP_COMMIT();
    unsigned swk = (unsigned)__cvta_generic_to_shared(sWkv);
    const float4* gk = (const float4*)(Wk + et*20480);
#pragma unroll
    for (int r = 0; r < 10; ++r) cp16(swk + (tid + r*512)*16, gk + tid + r*512);
    CP_COMMIT();
  }

  const int warp = tid >> 5, lane = tid & 31;

  // ---------------- Phase A: dia + LayerNorm (transposed writes) ----------------
  for (int c = warp; c < CSZ; c += 16) {
    const int e = sEid[c];
    if (e < 0) {
#pragma unroll
      for (int kk = 0; kk < 4; ++kk) sDd[(lane + 32*kk)*66 + c] = 0.f;
#pragma unroll
      for (int kk = 0; kk < 5; ++kk) sDs[(lane + 32*kk)*66 + c] = 0.f;
      continue;
    }
    const float t = date[e];
    const int s = src_idx[e];
    const int d = sDst[c];

    // dst side (128 dims)
    float xd[4];
#pragma unroll
    for (int kk = 0; kk < 4; ++kk) xd[kk] = src_h[d*128 + lane + 32*kk];
    xd[0] *= __sinf(src_tw[d*32+lane]*t + src_tb[d*32+lane]);
    float mu = warp_sum(xd[0]+xd[1]+xd[2]+xd[3]) * (1.f/128.f);
    float vv = 0.f;
#pragma unroll
    for (int kk = 0; kk < 4; ++kk) { float dl = xd[kk]-mu; vv = fmaf(dl,dl,vv); }
    float rs = rsqrtf(warp_sum(vv)*(1.f/128.f) + 1e-5f);
#pragma unroll
    for (int kk = 0; kk < 4; ++kk) {
      int i = lane + 32*kk;
      sDd[i*66 + c] = (xd[kk]-mu)*rs*dg[i] + db[i];
    }

    // src side (160 dims)
    float xs[5];
#pragma unroll
    for (int kk = 0; kk < 4; ++kk) xs[kk] = src_h[s*128 + lane + 32*kk];
    xs[0] *= __sinf(src_tw[s*32+lane]*t + src_tb[s*32+lane]);
    xs[4] = edge_h[e*32 + lane];
    mu = warp_sum(xs[0]+xs[1]+xs[2]+xs[3]+xs[4]) * (1.f/160.f);
    vv = 0.f;
#pragma unroll
    for (int kk = 0; kk < 5; ++kk) { float dl = xs[kk]-mu; vv = fmaf(dl,dl,vv); }
    rs = rsqrtf(warp_sum(vv)*(1.f/160.f) + 1e-5f);
#pragma unroll
    for (int kk = 0; kk < 5; ++kk) {
      int i = lane + 32*kk;
      sDs[i*66 + c] = (xs[kk]-mu)*rs*sg[i] + sb[i];
    }
  }
  CP_WAIT0();
  __syncthreads();

  // ---------------- Phase B: q/k matvecs (FFMA2, edges packed in pairs) ----------
  const int col0 = tid & 63, col1 = col0 + 64;
  const int eb = (tid >> 6) * 8;     // 8 edges = 4 pairs per thread group

  ull qa[4][2];
#pragma unroll
  for (int p = 0; p < 4; ++p) { qa[p][0] = 0ull; qa[p][1] = 0ull; }
#pragma unroll 2
  for (int i = 0; i < 128; ++i) {
    ull w0 = splat2(sWq[i*128 + col0]);
    ull w1 = splat2(sWq[i*128 + col1]);
    const ull* dp = (const ull*)(sDd + i*66 + eb);
#pragma unroll
    for (int p = 0; p < 4; ++p) {
      ull d = dp[p];
      ffma2(qa[p][0], d, w0);
      ffma2(qa[p][1], d, w1);
    }
  }

  ull ka[4][2];
#pragma unroll
  for (int p = 0; p < 4; ++p) { ka[p][0] = 0ull; ka[p][1] = 0ull; }
#pragma unroll 2
  for (int i = 0; i < 160; ++i) {
    ull w0 = splat2(sWkv[i*128 + col0]);
    ull w1 = splat2(sWkv[i*128 + col1]);
    const ull* dp = (const ull*)(sDs + i*66 + eb);
#pragma unroll
    for (int p = 0; p < 4; ++p) {
      ull d = dp[p];
      ffma2(ka[p][0], d, w0);
      ffma2(ka[p][1], d, w1);
    }
  }
  __syncthreads();   // all reads of sWkv done -> safe to overwrite with Wv

  // prefetch Wv over the logits phase
  {
    unsigned swk = (unsigned)__cvta_generic_to_shared(sWkv);
    const float4* gv = (const float4*)(Wv + et*20480);
#pragma unroll
    for (int r = 0; r < 10; ++r) cp16(swk + (tid + r*512)*16, gv + tid + r*512);
    CP_COMMIT();
  }

  // ---- logits -> exp -> denominators ----
  const int hl = col0 >> 4, hh = hl + 4;
  const float scl = 0.0883883476483184f; // 1/sqrt(128)
#pragma unroll
  for (int p = 0; p < 4; ++p) {
    ull pr0 = fmul2(qa[p][0], ka[p][0]);
    ull pr1 = fmul2(qa[p][1], ka[p][1]);
#pragma unroll
    for (int o = 1; o <= 8; o <<= 1) {
      pr0 = fadd2(pr0, __shfl_xor_sync(0xffffffffu, pr0, o));
      pr1 = fadd2(pr1, __shfl_xor_sync(0xffffffffu, pr1, o));
    }
    if ((lane & 15) == 0) {
      int e0 = eb + 2*p, e1 = e0 + 1;
      float2 a0 = unpk2(pr0);   // head hl, edges e0/e1
      float2 a1 = unpk2(pr1);   // head hh
      float x00 = __expf(a0.x*scl), x01 = __expf(a0.y*scl);
      float x10 = __expf(a1.x*scl), x11 = __expf(a1.y*scl);
      sEx[e0*8 + hl] = x00;  sEx[e1*8 + hl] = x01;
      sEx[e0*8 + hh] = x10;  sEx[e1*8 + hh] = x11;
      if (sEid[e0] >= 0) {
        atomicAdd(&g_denom[sDst[e0]*8 + hl], x00);
        atomicAdd(&g_denom[sDst[e0]*8 + hh], x10);
      }
      if (sEid[e1] >= 0) {
        atomicAdd(&g_denom[sDst[e1]*8 + hl], x01);
        atomicAdd(&g_denom[sDst[e1]*8 + hh], x11);
      }
    }
  }
  CP_WAIT0();
  __syncthreads();

  // ---- v matvec + weighted scatter ----
  ull va[4][2];
#pragma unroll
  for (int p = 0; p < 4; ++p) { va[p][0] = 0ull; va[p][1] = 0ull; }
#pragma unroll 2
  for (int i = 0; i < 160; ++i) {
    ull w0 = splat2(sWkv[i*128 + col0]);
    ull w1 = splat2(sWkv[i*128 + col1]);
    const ull* dp = (const ull*)(sDs + i*66 + eb);
#pragma unroll
    for (int p = 0; p < 4; ++p) {
      ull d = dp[p];
      ffma2(va[p][0], d, w0);
      ffma2(va[p][1], d, w1);
    }
  }
#pragma unroll
  for (int p = 0; p < 4; ++p) {
    int e0 = eb + 2*p, e1 = e0 + 1;
    float2 v0 = unpk2(va[p][0]);   // col0, edges e0/e1
    float2 v1 = unpk2(va[p][1]);   // col1
    if (sEid[e0] >= 0) {
      atomicAdd(&g_num[sDst[e0]*128 + col0], v0.x * sEx[e0*8 + hl]);
      atomicAdd(&g_num[sDst[e0]*128 + col1], v1.x * sEx[e0*8 + hh]);
    }
    if (sEid[e1] >= 0) {
      atomicAdd(&g_num[sDst[e1]*128 + col0], v0.y * sEx[e1*8 + hl]);
      atomicAdd(&g_num[sDst[e1]*128 + col1], v1.y * sEx[e1*8 + hh]);
    }
  }
}

// Output kernel: softmax divide + bias + typed linear + gated skip blend.
__global__ void __launch_bounds__(128) k_out(
    const float* __restrict__ src_h, const int* __restrict__ ntype,
    const float* __restrict__ Wa, const float* __restrict__ h_bias,
    const float* __restrict__ skip, float* __restrict__ out, int M)
{
  extern __shared__ float smem[];
  float* sWa = smem;          // 128*128
  float* sh  = smem + 16384;  // 128
  const int tt  = blockIdx.y;
  const int tid = threadIdx.x;
  {
    const float4* srcw = (const float4*)(Wa + tt*16384);
    for (int idx = tid; idx < 4096; idx += 128) ((float4*)sWa)[idx] = srcw[idx];
  }
  const float gate = 1.f / (1.f + __expf(-skip[tt]));
  const float bias = h_bias[tt*128 + tid];
  __syncthreads();

  const int m1 = min((blockIdx.x + 1) * CSZ, M);
  for (int m = blockIdx.x * CSZ; m < m1; ++m) {
    if (ntype[m] != tt) continue;          // uniform across block
    float dden = g_denom[m*8 + (tid >> 4)];
    float hv = (dden > 0.f) ? g_num[m*128 + tid] / dden : 0.f;  // isolated nodes
    sh[tid] = hv + bias;
    __syncthreads();
    float a0 = 0.f, a1 = 0.f, a2 = 0.f, a3 = 0.f;
#pragma unroll
    for (int i = 0; i < 128; i += 4) {
      a0 = fmaf(sh[i+0], sWa[(i+0)*128 + tid], a0);
      a1 = fmaf(sh[i+1], sWa[(i+1)*128 + tid], a1);
      a2 = fmaf(sh[i+2], sWa[(i+2)*128 + tid], a2);
      a3 = fmaf(sh[i+3], sWa[(i+3)*128 + tid], a3);
    }
    out[m*128 + tid] = ((a0+a1)+(a2+a3))*gate + src_h[m*128 + tid]*(1.f - gate);
    __syncthreads();
  }
}

extern "C" void kernel_launch(void* const* d_in, const int* in_sizes, int n_in,
                              void* d_out, int out_size) {
  const float* src_h  = (const float*)d_in[0];
  const float* src_tw = (const float*)d_in[1];
  const float* src_tb = (const float*)d_in[2];
  const float* edge_h = (const float*)d_in[3];
  const float* date   = (const float*)d_in[4];
  const int*   src_idx= (const int*)d_in[5];
  const int*   dst_idx= (const int*)d_in[6];
  const int*   etype  = (const int*)d_in[7];
  const int*   ntype  = (const int*)d_in[8];
  const float* Wq     = (const float*)d_in[9];
  const float* Wk     = (const float*)d_in[10];
  const float* Wv     = (const float*)d_in[11];
  const float* Wa     = (const float*)d_in[12];
  const float* h_bias = (const float*)d_in[13];
  const float* skip   = (const float*)d_in[14];
  const float* sg     = (const float*)d_in[15];
  const float* sb     = (const float*)d_in[16];
  const float* dg     = (const float*)d_in[17];
  const float* db     = (const float*)d_in[18];
  float* out = (float*)d_out;

  const int E = in_sizes[4];   // date
  const int M = in_sizes[8];   // ntype
  const int T = in_sizes[14];  // skip

  const int SMEM1 = (16384 + 20480 + 8448 + 10560 + 512) * 4 + 132 * 4; // ~221 KB
  const int SMEM3 = (16384 + 128) * 4;                                  // ~66 KB
  cudaFuncSetAttribute(k_edge, cudaFuncAttributeMaxDynamicSharedMemorySize, SMEM1);
  cudaFuncSetAttribute(k_out,  cudaFuncAttributeMaxDynamicSharedMemorySize, SMEM3);

  int initN = M * 128; if (PCAP > initN) initN = PCAP;
  k_init<<<(initN + 255)/256, 256>>>(M, PCAP);
  k_count<<<128, 256>>>(etype, E);
  k_scan<<<1, 1>>>();
  k_scatter<<<(E + 1023)/1024, 256>>>(etype, E);

  const int nb1 = (E + CSZ - 1)/CSZ + RTYPES;
  k_edge<<<nb1, 512, SMEM1>>>(src_h, src_tw, src_tb, edge_h, date,
                              src_idx, dst_idx, etype, Wq, Wk, Wv,
                              sg, sb, dg, db);

  dim3 g3((M + CSZ - 1)/CSZ, T);
  k_out<<<g3, 128, SMEM3>>>(src_h, ntype, Wa, h_bias, skip, out, M);
}

// round 6
// speedup vs baseline: 2.2077x; 2.0210x over previous
#include <cuda_runtime.h>
#include <cuda_bf16.h>
#include <cstdint>

#define RTYPES 8
#define CSZ 128
#define MCAP 10000
#define ECAP 100000
#define PCAP (ECAP + RTYPES*CSZ)

// ---------------- device scratch (no runtime alloc allowed) ----------------
__device__ float g_num[MCAP*128];
__device__ float g_denom[MCAP*8];
__device__ int   g_perm[PCAP];
__device__ int   g_counts[RTYPES];
__device__ int   g_cursor[RTYPES];
// Pre-swizzled bf16 hi/lo weight images (K-major SW128 blocked atoms)
__device__ __align__(16) unsigned char g_Bq[RTYPES*2*32768];  // K=128: 32KB/half
__device__ __align__(16) unsigned char g_Bk[RTYPES*2*49152];  // K=192 alloc (160 used)
__device__ __align__(16) unsigned char g_Bv[RTYPES*2*49152];

// ---------------- SMEM byte layout for k_edge ----------------
#define OFF_AD_HI 0          // A_d hi  (128x128 bf16 swizzled) 32768
#define OFF_AD_LO 32768
#define OFF_AS_HI 65536      // A_s hi  (128x192 alloc)        49152
#define OFF_AS_LO 114688
#define OFF_B     163840     // B half stage                    49152
#define OFF_EX    212992     // float[128*8]                    4096
#define OFF_DST   217088     // int[128]                        512
#define OFF_META  217600
#define SMEM_EDGE 217664
// bounce buffer overlays A_d region (free by then): 128*128 fp32 xor-swizzled

typedef unsigned char uchar;

__device__ __forceinline__ float warp_sum(float v) {
#pragma unroll
  for (int o = 16; o; o >>= 1) v += __shfl_xor_sync(0xffffffffu, v, o);
  return v;
}

// blocked-atom K-major SW128 byte offset: atom = 8 rows x 64 bf16 (1024B),
// 16 m-atoms, k-atoms stride 16*1024.
__host__ __device__ __forceinline__ uint32_t koff(int m, int k) {
  uint32_t off = (uint32_t)(((m >> 3) + (k >> 6) * 16) * 1024 + (m & 7) * 128 + (k & 63) * 2);
  return off ^ ((off >> 3) & 0x70);
}
__device__ __forceinline__ uint32_t koff2(uint32_t rowbase, int k) {
  uint32_t off = rowbase + ((k >> 6) << 14) + ((k & 63) << 1);
  return off ^ ((off >> 3) & 0x70);
}

__device__ __forceinline__ void cp16(uint32_t dst, const void* src) {
  asm volatile("cp.async.cg.shared.global [%0], [%1], 16;" :: "r"(dst), "l"(src));
}
#define CP_COMMIT() asm volatile("cp.async.commit_group;")
#define CP_WAIT0()  asm volatile("cp.async.wait_group 0;")

__device__ __forceinline__ void ldsm4(uint32_t* r, uint32_t a) {
  asm volatile("ldmatrix.sync.aligned.m8n8.x4.shared.b16 {%0,%1,%2,%3}, [%4];"
    : "=r"(r[0]), "=r"(r[1]), "=r"(r[2]), "=r"(r[3]) : "r"(a));
}
__device__ __forceinline__ void mma16816(float* c, const uint32_t* a, const uint32_t* b) {
  asm volatile("mma.sync.aligned.m16n8k16.row.col.f32.bf16.bf16.f32 "
    "{%0,%1,%2,%3}, {%4,%5,%6,%7}, {%8,%9}, {%0,%1,%2,%3};"
    : "+f"(c[0]), "+f"(c[1]), "+f"(c[2]), "+f"(c[3])
    : "r"(a[0]), "r"(a[1]), "r"(a[2]), "r"(a[3]), "r"(b[0]), "r"(b[1]));
}

// One compensation pass: C[128x128] += A[128xK] @ B[128xK]^T, warp-tile 32x64.
__device__ __forceinline__ void gemm_pass(
    uint32_t aB, uint32_t bB, int nk, int m0, int n0, int lane,
    float acc[2][8][4])
{
  const int r0 = m0 + (lane & 15);
  const int r1 = r0 + 16;
  const uint32_t arb0 = (uint32_t)(((r0 >> 3) << 10) + ((r0 & 7) << 7));
  const uint32_t arb1 = (uint32_t)(((r1 >> 3) << 10) + ((r1 & 7) << 7));
  const int ak = (lane >> 4) << 3;
  const int bn = n0 + (lane & 7) + ((lane >> 4) << 3);
  const int bk = ((lane >> 3) & 1) << 3;
  uint32_t brb[4];
#pragma unroll
  for (int p = 0; p < 4; ++p) {
    int n = bn + p * 16;
    brb[p] = (uint32_t)(((n >> 3) << 10) + ((n & 7) << 7));
  }
  for (int ks = 0; ks < nk; ++ks) {
    const int k0 = ks << 4;
    uint32_t A0[4], A1[4], B[4][4];
    ldsm4(A0, aB + koff2(arb0, k0 + ak));
    ldsm4(A1, aB + koff2(arb1, k0 + ak));
#pragma unroll
    for (int p = 0; p < 4; ++p) ldsm4(B[p], bB + koff2(brb[p], k0 + bk));
#pragma unroll
    for (int p = 0; p < 4; ++p) {
      mma16816(acc[0][2*p],   A0, &B[p][0]);
      mma16816(acc[0][2*p+1], A0, &B[p][2]);
      mma16816(acc[1][2*p],   A1, &B[p][0]);
      mma16816(acc[1][2*p+1], A1, &B[p][2]);
    }
  }
}

__device__ __forceinline__ void stageB(uint32_t dst, const uchar* src, int bytes, int tid) {
  for (int o = tid * 16; o < bytes; o += 4096) cp16(dst + o, src + o);
  CP_COMMIT();
}

// ================= fused init + count + weight-image prep =================
__global__ void __launch_bounds__(256) k_prep(
    const int* __restrict__ etype, int E, int M,
    const float* __restrict__ Wq, const float* __restrict__ Wk,
    const float* __restrict__ Wv, int NBI)
{
  __shared__ int loc[RTYPES];
  const int bid = blockIdx.x, tid = threadIdx.x;
  if (bid < NBI) {
    int i = bid * 256 + tid;
    if (i < M*128) g_num[i] = 0.f;
    if (i < M*8)   g_denom[i] = 0.f;
    if (i < PCAP)  g_perm[i] = -1;
    if (i < RTYPES) { g_counts[i] = 0; g_cursor[i] = 0; }
    return;
  }
  if (bid < NBI + 128) {
    if (tid < RTYPES) loc[tid] = 0;
    __syncthreads();
    for (int i = (bid - NBI)*256 + tid; i < E; i += 128*256)
      atomicAdd(&loc[etype[i]], 1);
    __syncthreads();
    if (tid < RTYPES && loc[tid]) atomicAdd(&g_counts[tid], loc[tid]);
    return;
  }
  int idx = (bid - NBI - 128) * 256 + tid;
  float val; uchar* hbase; uint32_t off; int half_stride;
  if (idx < 131072) {
    int r = idx >> 14, rem = idx & 16383, k = rem >> 7, n = rem & 127;
    val = Wq[r*16384 + k*128 + n];
    hbase = g_Bq + r*65536; half_stride = 32768; off = koff(n, k);
  } else if (idx < 131072 + 196608) {
    int i2 = idx - 131072;
    int r = i2 / 24576, rem = i2 % 24576, k = rem >> 7, n = rem & 127;
    val = (k < 160) ? Wk[r*20480 + k*128 + n] : 0.f;
    hbase = g_Bk + r*98304; half_stride = 49152; off = koff(n, k);
  } else {
    int i3 = idx - 131072 - 196608;
    if (i3 >= 196608) return;
    int r = i3 / 24576, rem = i3 % 24576, k = rem >> 7, n = rem & 127;
    val = (k < 160) ? Wv[r*20480 + k*128 + n] : 0.f;
    hbase = g_Bv + r*98304; half_stride = 49152; off = koff(n, k);
  }
  __nv_bfloat16 hi = __float2bfloat16(val);
  __nv_bfloat16 lo = __float2bfloat16(val - __bfloat162float(hi));
  *(__nv_bfloat16*)(hbase + off) = hi;
  *(__nv_bfloat16*)(hbase + half_stride + off) = lo;
}

__global__ void k_scan() {
  int b = 0;
  for (int r = 0; r < RTYPES; ++r) {
    g_cursor[r] = b;
    b += ((g_counts[r] + CSZ - 1) / CSZ) * CSZ;
  }
}

__global__ void k_scatter(const int* __restrict__ etype, int E) {
  __shared__ int loc[RTYPES], base[RTYPES];
  const int t = threadIdx.x;
  if (t < RTYPES) loc[t] = 0;
  __syncthreads();
  const int start = blockIdx.x * 1024;
  const int end = min(start + 1024, E);
  for (int i = start + t; i < end; i += 256) atomicAdd(&loc[etype[i]], 1);
  __syncthreads();
  if (t < RTYPES) { base[t] = loc[t] ? atomicAdd(&g_cursor[t], loc[t]) : 0; loc[t] = 0; }
  __syncthreads();
  for (int i = start + t; i < end; i += 256) {
    int r = etype[i];
    g_perm[base[r] + atomicAdd(&loc[r], 1)] = i;
  }
}

// ================= main edge kernel: warp-MMA bf16 3-pass =================
__global__ void __launch_bounds__(256, 1) k_edge(
    const float* __restrict__ src_h, const float* __restrict__ src_tw,
    const float* __restrict__ src_tb, const float* __restrict__ edge_h,
    const float* __restrict__ date, const int* __restrict__ src_idx,
    const int* __restrict__ dst_idx, const int* __restrict__ etype,
    const float* __restrict__ sg, const float* __restrict__ sb,
    const float* __restrict__ dg, const float* __restrict__ db)
{
  extern __shared__ __align__(1024) char sm[];
  float* sEx  = (float*)(sm + OFF_EX);
  int*   sDst = (int*)(sm + OFF_DST);
  int*   sMeta = (int*)(sm + OFF_META);
  const uint32_t smb = (uint32_t)__cvta_generic_to_shared(sm);

  const int tid = threadIdx.x, wid = tid >> 5, lane = tid & 31;
  const int chunk = blockIdx.x * CSZ;

  if (tid < CSZ) {
    int e = g_perm[chunk + tid];
    sDst[tid] = (e >= 0) ? dst_idx[e] : -1;
  }
  if (tid == 0) {
    int e0 = g_perm[chunk];
    sMeta[0] = (e0 >= 0) ? etype[e0] : -1;
  }
  __syncthreads();
  const int et = sMeta[0];
  if (et < 0) return;

  stageB(smb + OFF_B, g_Bq + et*65536, 32768, tid);  // Wq hi over Phase A

  // ---------------- Phase A: dia + LayerNorm -> bf16 hi/lo swizzled ----------------
  for (int c = wid; c < CSZ; c += 8) {
    const int e = g_perm[chunk + c];
    if (e < 0) continue;   // pad rows: garbage is row-local, guarded at scatter
    const float t = date[e];
    const int s = src_idx[e];
    const int d = sDst[c];

    float xd[4];
#pragma unroll
    for (int kk = 0; kk < 4; ++kk) xd[kk] = src_h[d*128 + lane + 32*kk];
    xd[0] *= __sinf(src_tw[d*32+lane]*t + src_tb[d*32+lane]);
    float mu = warp_sum(xd[0]+xd[1]+xd[2]+xd[3]) * (1.f/128.f);
    float vv = 0.f;
#pragma unroll
    for (int kk = 0; kk < 4; ++kk) { float dl = xd[kk]-mu; vv = fmaf(dl,dl,vv); }
    float rs = rsqrtf(warp_sum(vv)*(1.f/128.f) + 1e-5f);
#pragma unroll
    for (int kk = 0; kk < 4; ++kk) {
      int i = lane + 32*kk;
      float v = (xd[kk]-mu)*rs*dg[i] + db[i];
      __nv_bfloat16 hi = __float2bfloat16(v);
      __nv_bfloat16 lo = __float2bfloat16(v - __bfloat162float(hi));
      uint32_t o = koff(c, i);
      *(__nv_bfloat16*)(sm + OFF_AD_HI + o) = hi;
      *(__nv_bfloat16*)(sm + OFF_AD_LO + o) = lo;
    }

    float xs[5];
#pragma unroll
    for (int kk = 0; kk < 4; ++kk) xs[kk] = src_h[s*128 + lane + 32*kk];
    xs[0] *= __sinf(src_tw[s*32+lane]*t + src_tb[s*32+lane]);
    xs[4] = edge_h[e*32 + lane];
    mu = warp_sum(xs[0]+xs[1]+xs[2]+xs[3]+xs[4]) * (1.f/160.f);
    vv = 0.f;
#pragma unroll
    for (int kk = 0; kk < 5; ++kk) { float dl = xs[kk]-mu; vv = fmaf(dl,dl,vv); }
    rs = rsqrtf(warp_sum(vv)*(1.f/160.f) + 1e-5f);
#pragma unroll
    for (int kk = 0; kk < 5; ++kk) {
      int i = lane + 32*kk;
      float v = (xs[kk]-mu)*rs*sg[i] + sb[i];
      __nv_bfloat16 hi = __float2bfloat16(v);
      __nv_bfloat16 lo = __float2bfloat16(v - __bfloat162float(hi));
      uint32_t o = koff(c, i);
      *(__nv_bfloat16*)(sm + OFF_AS_HI + o) = hi;
      *(__nv_bfloat16*)(sm + OFF_AS_LO + o) = lo;
    }
  }
  CP_WAIT0();
  __syncthreads();

  const int m0 = (wid >> 1) * 32;
  const int n0 = (wid & 1) * 64;
  const uint32_t aDhi = smb + OFF_AD_HI, aDlo = smb + OFF_AD_LO;
  const uint32_t aShi = smb + OFF_AS_HI, aSlo = smb + OFF_AS_LO;
  const uint32_t bS = smb + OFF_B;

  // ---- q GEMM (3 passes) ----
  float accQ[2][8][4];
#pragma unroll
  for (int a = 0; a < 2; ++a)
#pragma unroll
    for (int b = 0; b < 8; ++b)
#pragma unroll
      for (int c = 0; c < 4; ++c) accQ[a][b][c] = 0.f;
  gemm_pass(aDhi, bS, 8, m0, n0, lane, accQ);
  gemm_pass(aDlo, bS, 8, m0, n0, lane, accQ);
  __syncthreads();
  stageB(bS, g_Bq + et*65536 + 32768, 32768, tid);
  CP_WAIT0(); __syncthreads();
  gemm_pass(aDhi, bS, 8, m0, n0, lane, accQ);
  __syncthreads();

  // ---- k GEMM (3 passes), K=160 -> nk=10 ----
  stageB(bS, g_Bk + et*98304, 49152, tid);
  CP_WAIT0(); __syncthreads();
  float accC[2][8][4];
#pragma unroll
  for (int a = 0; a < 2; ++a)
#pragma unroll
    for (int b = 0; b < 8; ++b)
#pragma unroll
      for (int c = 0; c < 4; ++c) accC[a][b][c] = 0.f;
  gemm_pass(aShi, bS, 10, m0, n0, lane, accC);
  gemm_pass(aSlo, bS, 10, m0, n0, lane, accC);
  __syncthreads();
  stageB(bS, g_Bk + et*98304 + 49152, 49152, tid);
  CP_WAIT0(); __syncthreads();
  gemm_pass(aShi, bS, 10, m0, n0, lane, accC);
  __syncthreads();

  stageB(bS, g_Bv + et*98304, 49152, tid);  // Wv hi over logits epilogue

  // ---- logits: per-head q.k dots via quad shuffles; exp; denominators ----
  {
    const float scl = 0.0883883476483184f;  // 1/sqrt(128)
#pragma unroll
    for (int mi = 0; mi < 2; ++mi)
#pragma unroll
      for (int rh = 0; rh < 2; ++rh) {
        int row = m0 + mi*16 + rh*8 + (lane >> 2);
#pragma unroll
        for (int hl = 0; hl < 4; ++hl) {
          float p = accQ[mi][2*hl][2*rh]    * accC[mi][2*hl][2*rh]
                  + accQ[mi][2*hl][2*rh+1]  * accC[mi][2*hl][2*rh+1]
                  + accQ[mi][2*hl+1][2*rh]  * accC[mi][2*hl+1][2*rh]
                  + accQ[mi][2*hl+1][2*rh+1]* accC[mi][2*hl+1][2*rh+1];
          p += __shfl_xor_sync(0xffffffffu, p, 1);
          p += __shfl_xor_sync(0xffffffffu, p, 2);
          if ((lane & 3) == 0) {
            float ex = __expf(p * scl);
            int head = (n0 >> 4) + hl;
            sEx[row*8 + head] = ex;
            int d = sDst[row];
            if (d >= 0) atomicAdd(&g_denom[d*8 + head], ex);
          }
        }
      }
  }
  CP_WAIT0(); __syncthreads();

  // ---- v GEMM (3 passes) ----
#pragma unroll
  for (int a = 0; a < 2; ++a)
#pragma unroll
    for (int b = 0; b < 8; ++b)
#pragma unroll
      for (int c = 0; c < 4; ++c) accC[a][b][c] = 0.f;
  gemm_pass(aShi, bS, 10, m0, n0, lane, accC);
  gemm_pass(aSlo, bS, 10, m0, n0, lane, accC);
  __syncthreads();
  stageB(bS, g_Bv + et*98304 + 49152, 49152, tid);
  CP_WAIT0(); __syncthreads();
  gemm_pass(aShi, bS, 10, m0, n0, lane, accC);
  __syncthreads();   // all warps done; A_d region reusable as bounce

  // ---- v epilogue: scale by ex -> xor-swizzled bounce -> coalesced scatter ----
  {
    float* bounce = (float*)sm;   // 128x128 fp32, col ^ ((row&7)<<2)
#pragma unroll
    for (int mi = 0; mi < 2; ++mi)
#pragma unroll
      for (int rh = 0; rh < 2; ++rh) {
        int row = m0 + mi*16 + rh*8 + (lane >> 2);
#pragma unroll
        for (int ni = 0; ni < 8; ++ni) {
          int col = n0 + ni*8 + (lane & 3)*2;
          int head = (n0 >> 4) + (ni >> 1);
          float ex = sEx[row*8 + head];
          float2 v2 = make_float2(accC[mi][ni][2*rh]*ex, accC[mi][ni][2*rh+1]*ex);
          *(float2*)&bounce[row*128 + (col ^ ((row & 7) << 2))] = v2;
        }
      }
  }
  __syncthreads();
  {
    const float* bounce = (const float*)sm;
    for (int i = 0; i < 16; ++i) {
      int e = wid*16 + i;
      int d = sDst[e];
      if (d < 0) continue;
#pragma unroll
      for (int j2 = 0; j2 < 4; ++j2) {
        int col = lane + 32*j2;
        atomicAdd(&g_num[d*128 + col], bounce[e*128 + (col ^ ((e & 7) << 2))]);
      }
    }
  }
}

// ================= output kernel =================
__global__ void __launch_bounds__(128) k_out(
    const float* __restrict__ src_h, const int* __restrict__ ntype,
    const float* __restrict__ Wa, const float* __restrict__ h_bias,
    const float* __restrict__ skip, float* __restrict__ out, int M)
{
  extern __shared__ float smem[];
  float* sWa = smem;
  float* sh  = smem + 16384;
  const int tt  = blockIdx.y;
  const int tid = threadIdx.x;
  {
    const float4* srcw = (const float4*)(Wa + tt*16384);
    for (int idx = tid; idx < 4096; idx += 128) ((float4*)sWa)[idx] = srcw[idx];
  }
  const float gate = 1.f / (1.f + __expf(-skip[tt]));
  const float bias = h_bias[tt*128 + tid];
  __syncthreads();

  const int m1 = min((int)(blockIdx.x + 1) * 64, M);
  for (int m = blockIdx.x * 64; m < m1; ++m) {
    if (ntype[m] != tt) continue;
    float dden = g_denom[m*8 + (tid >> 4)];
    float hv = (dden > 0.f) ? g_num[m*128 + tid] / dden : 0.f;
    sh[tid] = hv + bias;
    __syncthreads();
    float a0 = 0.f, a1 = 0.f, a2 = 0.f, a3 = 0.f;
#pragma unroll
    for (int i = 0; i < 128; i += 4) {
      a0 = fmaf(sh[i+0], sWa[(i+0)*128 + tid], a0);
      a1 = fmaf(sh[i+1], sWa[(i+1)*128 + tid], a1);
      a2 = fmaf(sh[i+2], sWa[(i+2)*128 + tid], a2);
      a3 = fmaf(sh[i+3], sWa[(i+3)*128 + tid], a3);
    }
    out[m*128 + tid] = ((a0+a1)+(a2+a3))*gate + src_h[m*128 + tid]*(1.f - gate);
    __syncthreads();
  }
}

extern "C" void kernel_launch(void* const* d_in, const int* in_sizes, int n_in,
                              void* d_out, int out_size) {
  const float* src_h  = (const float*)d_in[0];
  const float* src_tw = (const float*)d_in[1];
  const float* src_tb = (const float*)d_in[2];
  const float* edge_h = (const float*)d_in[3];
  const float* date   = (const float*)d_in[4];
  const int*   src_idx= (const int*)d_in[5];
  const int*   dst_idx= (const int*)d_in[6];
  const int*   etype  = (const int*)d_in[7];
  const int*   ntype  = (const int*)d_in[8];
  const float* Wq     = (const float*)d_in[9];
  const float* Wk     = (const float*)d_in[10];
  const float* Wv     = (const float*)d_in[11];
  const float* Wa     = (const float*)d_in[12];
  const float* h_bias = (const float*)d_in[13];
  const float* skip   = (const float*)d_in[14];
  const float* sg     = (const float*)d_in[15];
  const float* sb     = (const float*)d_in[16];
  const float* dg     = (const float*)d_in[17];
  const float* db     = (const float*)d_in[18];
  float* out = (float*)d_out;

  const int E = in_sizes[4];
  const int M = in_sizes[8];
  const int T = in_sizes[14];

  cudaFuncSetAttribute(k_edge, cudaFuncAttributeMaxDynamicSharedMemorySize, SMEM_EDGE);
  cudaFuncSetAttribute(k_out,  cudaFuncAttributeMaxDynamicSharedMemorySize, (16384+128)*4);

  int initN = M * 128; if (PCAP > initN) initN = PCAP;
  const int NBI = (initN + 255) / 256;
  const int NBP = (131072 + 196608 + 196608 + 255) / 256;  // 2048
  k_prep<<<NBI + 128 + NBP, 256>>>(etype, E, M, Wq, Wk, Wv, NBI);
  k_scan<<<1, 1>>>();
  k_scatter<<<(E + 1023)/1024, 256>>>(etype, E);

  const int nb = (E + CSZ - 1)/CSZ + RTYPES;   // k_edge is the 4th launch
  k_edge<<<nb, 256, SMEM_EDGE>>>(src_h, src_tw, src_tb, edge_h, date,
                                 src_idx, dst_idx, etype, sg, sb, dg, db);

  dim3 g3((M + 63)/64, T);
  k_out<<<g3, 128, (16384+128)*4>>>(src_h, ntype, Wa, h_bias, skip, out, M);
}